// round 14
// baseline (speedup 1.0000x reference)
#include <cuda_runtime.h>
#include <cuda_bf16.h>
#include <cstdint>

#define Nn 307
#define Cc 64
#define Tt 12
#define BT 96
#define NPAD 320
#define XC 128            // split cols: [hi(64) | lo(64)] = 256 B/row
#define TN (Tt * Nn)

// ---------------- scratch ----------------
__device__ __nv_bfloat16 g_Aspl[64 * 128];  // row e: [At_hi(c) | At_lo(c)], At[e][c]=A[c][e] scaled
__device__ float g_u[64], g_v[64], g_cconst[1];
__device__ float g_xu[BT * NPAD];
__device__ float g_xv[BT * NPAD];
// PRE-SWIZZLED split buffers (row-local swizzle, 256B rows)
__device__ __nv_bfloat16 g_Y[(size_t)BT * NPAD * XC];
__device__ __nv_bfloat16 g_X[(size_t)BT * NPAD * XC];

__device__ __forceinline__ uint32_t smem_u32(const void* p) {
    uint32_t a;
    asm("{ .reg .u64 t; cvta.to.shared.u64 t, %1; cvt.u32.u64 %0, t; }" : "=r"(a) : "l"(p));
    return a;
}
#define CPASYNC16(dst, src) \
    asm volatile("cp.async.cg.shared.global [%0], [%1], 16;" :: "r"(dst), "l"(src))
#define CPASYNC_WAIT() \
    asm volatile("cp.async.commit_group;\n\tcp.async.wait_group 0;" ::: "memory")

#define LDSM4(r0_, r1_, r2_, r3_, addr) \
    asm volatile("ldmatrix.sync.aligned.m8n8.x4.shared.b16 {%0,%1,%2,%3}, [%4];" \
        : "=r"(r0_), "=r"(r1_), "=r"(r2_), "=r"(r3_) : "r"(addr))

#define MMA16816(d, a, b0_, b1_) \
    asm volatile("mma.sync.aligned.m16n8k16.row.col.f32.bf16.bf16.f32 " \
        "{%0,%1,%2,%3}, {%4,%5,%6,%7}, {%8,%9}, {%0,%1,%2,%3};" \
        : "+f"((d)[0]), "+f"((d)[1]), "+f"((d)[2]), "+f"((d)[3]) \
        : "r"((a)[0]), "r"((a)[1]), "r"((a)[2]), "r"((a)[3]), "r"(b0_), "r"(b1_))

// ---------------- dummy: shifts ncu capture index onto attn/p1 ----------------
__global__ void dummy_kernel() {}

// ---------------- P0: Aᵀ split + u,v,c — float4 loads, 4 outputs/thread ----------------
__global__ void __launch_bounds__(256)
p0_kernel(const float* __restrict__ Wq, const float* __restrict__ bq,
          const float* __restrict__ Wk, const float* __restrict__ bk)
{
    int blk = blockIdx.x, tid = threadIdx.x;
    const float s = 0.35355339059327373f;   // 1/sqrt(8)
    if (blk < 4) {
        int c  = blk * 16 + (tid >> 4);
        int e0 = (tid & 15) * 4;
        float a0 = 0.f, a1 = 0.f, a2 = 0.f, a3 = 0.f;
        #pragma unroll
        for (int k = 0; k < 64; k++) {
            float wq = __ldg(&Wq[k * 64 + c]);
            float4 wk = __ldg((const float4*)&Wk[k * 64 + e0]);
            a0 += wq * wk.x; a1 += wq * wk.y; a2 += wq * wk.z; a3 += wq * wk.w;
        }
        float av[4] = {a0 * s, a1 * s, a2 * s, a3 * s};
        #pragma unroll
        for (int j = 0; j < 4; j++) {
            int e = e0 + j;
            __nv_bfloat16 h = __float2bfloat16(av[j]);
            __nv_bfloat16 l = __float2bfloat16(av[j] - __bfloat162float(h));
            g_Aspl[e * 128 + c]      = h;
            g_Aspl[e * 128 + 64 + c] = l;
        }
    } else {
        if (tid < 64) {
            float ua = 0.f;
            #pragma unroll
            for (int k = 0; k < 64; k++) ua += __ldg(&Wq[k * 64 + tid]) * __ldg(&bk[k]);
            g_u[tid] = ua * s;
        } else if (tid < 128) {
            int d = tid - 64;
            float va = 0.f;
            #pragma unroll
            for (int k = 0; k < 64; k++) va += __ldg(&Wk[k * 64 + d]) * __ldg(&bq[k]);
            g_v[d] = va * s;
        } else if (tid == 128) {
            float ca = 0.f;
            #pragma unroll
            for (int k = 0; k < 64; k++) ca += __ldg(&bq[k]) * __ldg(&bk[k]);
            g_cconst[0] = ca * s;
        }
    }
}

// ---------------- P1: convert x, Y via MMA (3-pass), xu/xv, pre-swizzled outputs ----------------
#define S1_XS  0
#define S1_XSP 32768
#define S1_A   65536
#define S1_UV  81920
#define S1_TOT 82560

__global__ void __launch_bounds__(256, 2)
p1_kernel(const float* __restrict__ x)
{
    extern __shared__ char smc[];
    float* xs = (float*)(smc + S1_XS);          // [c][n] stride 128
    float* uvs = (float*)(smc + S1_UV);
    int bt = blockIdx.x, rt = blockIdx.y;
    int b = bt / Tt, t = bt % Tt;
    int n0 = rt * 128;
    int tid = threadIdx.x, wid = tid >> 5, lane = tid & 31;
    int nrows = NPAD - n0; if (nrows > 128) nrows = 128;

    const float* xb = x + ((size_t)(b * Cc) * Tt + t) * Nn;
    for (int i = tid; i < 64 * 128; i += 256) {
        int c = i >> 7, n = i & 127;
        int ng = n0 + n;
        xs[i] = (ng < Nn) ? xb[(size_t)c * TN + ng] : 0.f;
    }
    {
        const uint4* asrc = (const uint4*)g_Aspl;
        uint4* adst = (uint4*)(smc + S1_A);
        for (int i = tid; i < 1024; i += 256) {
            int row = i >> 4, ci = i & 15;
            adst[(row << 4) + (ci ^ (row & 7))] = asrc[i];
        }
    }
    if (tid < 64) uvs[tid] = g_u[tid];
    else if (tid < 128) uvs[tid] = g_v[tid - 64];
    else if (tid == 128) uvs[128] = g_cconst[0];
    __syncthreads();

    // convert xs -> Xsplit (swizzled)
    for (int i = tid; i < 4096; i += 256) {
        int n = i & 127, cp = i >> 7;
        int c = cp * 2;
        float v0 = xs[c * 128 + n];
        float v1 = xs[(c + 1) * 128 + n];
        __nv_bfloat162 hh = __floats2bfloat162_rn(v0, v1);
        float l0 = v0 - __bfloat162float(hh.x);
        float l1 = v1 - __bfloat162float(hh.y);
        __nv_bfloat162 ll = __floats2bfloat162_rn(l0, l1);
        uint32_t base = (n << 8) + ((cp & 3) << 2);
        *(uint32_t*)(smc + S1_XSP + base + ((((cp >> 2))     ^ (n & 7)) << 4)) = *(uint32_t*)&hh;
        *(uint32_t*)(smc + S1_XSP + base + (((8 + (cp >> 2)) ^ (n & 7)) << 4)) = *(uint32_t*)&ll;
    }
    __syncthreads();

    // xu / xv + copy Xsplit out (raw, pre-swizzled)
    {
        int r = tid & 127;
        int ng = n0 + r;
        if (ng < NPAD) {
            float a = 0.f;
            int woff = (tid < 128) ? 0 : 64;
            #pragma unroll 16
            for (int c = 0; c < 64; c++) a += xs[c * 128 + r] * uvs[woff + c];
            if (tid < 128) g_xu[bt * NPAD + ng] = a;
            else           g_xv[bt * NPAD + ng] = a + uvs[128];
        }
    }
    {
        uint4* gx = (uint4*)(g_X + ((size_t)bt * NPAD + n0) * XC);
        const uint4* s4 = (const uint4*)(smc + S1_XSP);
        for (int i = tid; i < nrows * 16; i += 256) gx[i] = s4[i];
    }

    // Y = X·Aᵀ, 3-pass: (Xhi,Ahi),(Xhi,Alo),(Xlo,Ahi). Warps 4x2: M=32, N=32
    uint32_t smbX = smem_u32(smc + S1_XSP);
    uint32_t smbA = smem_u32(smc + S1_A);
    int wr = wid >> 1, wc = wid & 1;
    int aRow[2], bRow[2];
    #pragma unroll
    for (int mi = 0; mi < 2; mi++)
        aRow[mi] = wr * 32 + mi * 16 + ((lane >> 3) & 1) * 8 + (lane & 7);
    #pragma unroll
    for (int ni = 0; ni < 2; ni++)
        bRow[ni] = wc * 32 + ni * 16 + (lane >> 4) * 8 + (lane & 7);
    int aChf = lane >> 4, bChf = (lane >> 3) & 1;

    float accY[2][4][4];
    #pragma unroll
    for (int mi = 0; mi < 2; mi++)
        #pragma unroll
        for (int nq = 0; nq < 4; nq++)
            #pragma unroll
            for (int q = 0; q < 4; q++) accY[mi][nq][q] = 0.f;

    #pragma unroll
    for (int kk = 0; kk < 12; kk++) {
        int p = kk >> 2, q = kk & 3;
        int aBase = (p == 2 ? 8 : 0) + q * 2;   // X: lo on pass 2
        int bBase = (p == 1 ? 8 : 0) + q * 2;   // A: lo on pass 1
        uint32_t a[2][4], bb[2][4];
        #pragma unroll
        for (int mi = 0; mi < 2; mi++) {
            int r = aRow[mi];
            uint32_t ad = smbX + (r << 8) + (((aBase + aChf) ^ (r & 7)) << 4);
            LDSM4(a[mi][0], a[mi][1], a[mi][2], a[mi][3], ad);
        }
        #pragma unroll
        for (int ni = 0; ni < 2; ni++) {
            int r = bRow[ni];
            uint32_t bd = smbA + (r << 8) + (((bBase + bChf) ^ (r & 7)) << 4);
            LDSM4(bb[ni][0], bb[ni][1], bb[ni][2], bb[ni][3], bd);
        }
        #pragma unroll
        for (int mi = 0; mi < 2; mi++)
            #pragma unroll
            for (int ni = 0; ni < 2; ni++) {
                MMA16816(accY[mi][ni * 2],     a[mi], bb[ni][0], bb[ni][1]);
                MMA16816(accY[mi][ni * 2 + 1], a[mi], bb[ni][2], bb[ni][3]);
            }
    }
    __syncthreads();   // xs readers done -> stage overlay safe

    // split accY -> stage (swizzled), then copy out
    {
        char* stg = smc + S1_XS;
        #pragma unroll
        for (int mi = 0; mi < 2; mi++) {
            #pragma unroll
            for (int nq = 0; nq < 4; nq++) {
                int col = wc * 32 + nq * 8 + (lane & 3) * 2;
                #pragma unroll
                for (int h = 0; h < 2; h++) {
                    int rl = wr * 32 + mi * 16 + (lane >> 2) + h * 8;
                    float a0 = accY[mi][nq][h * 2], a1 = accY[mi][nq][h * 2 + 1];
                    __nv_bfloat162 hh = __floats2bfloat162_rn(a0, a1);
                    float l0 = a0 - __bfloat162float(hh.x);
                    float l1 = a1 - __bfloat162float(hh.y);
                    __nv_bfloat162 ll = __floats2bfloat162_rn(l0, l1);
                    uint32_t off = (col & 7) << 1;
                    *(uint32_t*)(stg + (rl << 8) + ((((col >> 3))     ^ (rl & 7)) << 4) + off) = *(uint32_t*)&hh;
                    *(uint32_t*)(stg + (rl << 8) + (((8 + (col >> 3)) ^ (rl & 7)) << 4) + off) = *(uint32_t*)&ll;
                }
            }
        }
    }
    __syncthreads();
    {
        uint4* gy = (uint4*)(g_Y + ((size_t)bt * NPAD + n0) * XC);
        const uint4* s4 = (const uint4*)(smc + S1_XS);
        for (int i = tid; i < nrows * 16; i += 256) gy[i] = s4[i];
    }
}

// ---------------- attn: cp.async load, 3-pass K=192 MMA, spill, softmax ----------------
#define SM_X 0               // 320*256 = 81920 (pre-swizzled)
#define SM_Y 81920           // 64*256  = 16384
#define SM_TOT 98304
#define SROW 328

__global__ void __launch_bounds__(256, 2)
attn_kernel(const int* __restrict__ mask, float* __restrict__ out)
{
    extern __shared__ char smc[];
    int tid = threadIdx.x, wid = tid >> 5, lane = tid & 31;
    int bt = blockIdx.x, mt = blockIdx.y;
    int b = bt / Tt;
    int r0 = mt * 64;

    // ---- raw async copies (already swizzled in gmem) ----
    {
        uint32_t xd = smem_u32(smc + SM_X);
        const uint4* xsrc = (const uint4*)(g_X + (size_t)bt * NPAD * XC);
        for (int i = tid; i < 5120; i += 256)
            CPASYNC16(xd + i * 16, xsrc + i);
        uint32_t yd = smem_u32(smc + SM_Y);
        const uint4* ysrc = (const uint4*)(g_Y + ((size_t)bt * NPAD + r0) * XC);
        for (int i = tid; i < 1024; i += 256)
            CPASYNC16(yd + i * 16, ysrc + i);
        CPASYNC_WAIT();
    }
    __syncthreads();

    int wr = wid >> 2, wc = wid & 3;
    int m0w = wr * 32, n0w = wc * 80;
    uint32_t smbY = smem_u32(smc + SM_Y);
    uint32_t smbX = smem_u32(smc + SM_X);

    int aRowL[2], bRow[5];
    #pragma unroll
    for (int mi = 0; mi < 2; mi++)
        aRowL[mi] = m0w + mi * 16 + ((lane >> 3) & 1) * 8 + (lane & 7);
    #pragma unroll
    for (int pi = 0; pi < 5; pi++)
        bRow[pi] = n0w + pi * 16 + (lane >> 4) * 8 + (lane & 7);
    int aChf = lane >> 4;
    int bChf = (lane >> 3) & 1;

    float acc[2][10][4];
    #pragma unroll
    for (int mi = 0; mi < 2; mi++)
        #pragma unroll
        for (int ni = 0; ni < 10; ni++)
            #pragma unroll
            for (int q = 0; q < 4; q++) acc[mi][ni][q] = 0.f;

    // 3-pass: (Yhi,Xhi),(Yhi,Xlo),(Ylo,Xhi)
    #pragma unroll
    for (int kk = 0; kk < 12; kk++) {
        int p = kk >> 2, q = kk & 3;
        int aBase = (p == 2 ? 8 : 0) + q * 2;   // Y: lo on pass 2
        int bBase = (p == 1 ? 8 : 0) + q * 2;   // X: lo on pass 1
        uint32_t a[2][4], bf[5][4];
        #pragma unroll
        for (int mi = 0; mi < 2; mi++) {
            int r = aRowL[mi];
            uint32_t ad = smbY + (r << 8) + (((aBase + aChf) ^ (r & 7)) << 4);
            LDSM4(a[mi][0], a[mi][1], a[mi][2], a[mi][3], ad);
        }
        #pragma unroll
        for (int pi = 0; pi < 5; pi++) {
            int r = bRow[pi];
            uint32_t bd = smbX + (r << 8) + (((bBase + bChf) ^ (r & 7)) << 4);
            LDSM4(bf[pi][0], bf[pi][1], bf[pi][2], bf[pi][3], bd);
        }
        #pragma unroll
        for (int mi = 0; mi < 2; mi++)
            #pragma unroll
            for (int pi = 0; pi < 5; pi++) {
                MMA16816(acc[mi][2 * pi],     a[mi], bf[pi][0], bf[pi][1]);
                MMA16816(acc[mi][2 * pi + 1], a[mi], bf[pi][2], bf[pi][3]);
            }
    }
    __syncthreads();

    // ---- spill scores ----
    float* S = (float*)smc;
    {
        int rbase = m0w + (lane >> 2);
        int cbase = n0w + (lane & 3) * 2;
        #pragma unroll
        for (int mi = 0; mi < 2; mi++) {
            #pragma unroll
            for (int ni = 0; ni < 10; ni++) {
                int c = cbase + ni * 8;
                *(float2*)&S[(rbase + mi * 16) * SROW + c]     = make_float2(acc[mi][ni][0], acc[mi][ni][1]);
                *(float2*)&S[(rbase + mi * 16 + 8) * SROW + c] = make_float2(acc[mi][ni][2], acc[mi][ni][3]);
            }
        }
    }
    __syncthreads();

    // ---- softmax (warp per row) ----
    float xv10[10];
    #pragma unroll
    for (int it = 0; it < 10; it++)
        xv10[it] = g_xv[bt * NPAD + lane + it * 32];

    for (int r = wid; r < 64; r += 8) {
        int n = r0 + r;
        if (n >= Nn) break;
        float xun = g_xu[bt * NPAD + n];
        const int* mrow = mask + ((size_t)b * Nn + n) * Nn;
        float v[10];
        float mx = -3.4e38f;
        #pragma unroll
        for (int it = 0; it < 10; it++) {
            int m = lane + it * 32;
            float s = -3.4e38f;
            if (m < Nn) s = mrow[m] ? (S[r * SROW + m] + xun + xv10[it]) : -1e9f;
            v[it] = s;
            mx = fmaxf(mx, s);
        }
        #pragma unroll
        for (int o = 16; o; o >>= 1)
            mx = fmaxf(mx, __shfl_xor_sync(0xffffffffu, mx, o));
        float ssum = 0.f;
        #pragma unroll
        for (int it = 0; it < 10; it++) {
            float e = __expf(v[it] - mx);
            v[it] = e;
            ssum += e;
        }
        #pragma unroll
        for (int o = 16; o; o >>= 1)
            ssum += __shfl_xor_sync(0xffffffffu, ssum, o);
        float inv = 1.0f / ssum;
        float* orow = out + ((size_t)bt * Nn + n) * Nn;
        #pragma unroll
        for (int it = 0; it < 10; it++) {
            int m = lane + it * 32;
            if (m < Nn) orow[m] = v[it] * inv;
        }
    }
}

extern "C" void kernel_launch(void* const* d_in, const int* in_sizes, int n_in,
                              void* d_out, int out_size)
{
    const float* x    = (const float*)d_in[0];
    const int*   mask = (const int*)  d_in[1];
    const float* Wq   = (const float*)d_in[2];
    const float* bq   = (const float*)d_in[3];
    const float* Wk   = (const float*)d_in[4];
    const float* bk   = (const float*)d_in[5];
    float* out = (float*)d_out;

    cudaFuncSetAttribute(p1_kernel, cudaFuncAttributeMaxDynamicSharedMemorySize, S1_TOT);
    cudaFuncSetAttribute(attn_kernel, cudaFuncAttributeMaxDynamicSharedMemorySize, SM_TOT);

    dummy_kernel<<<1, 32>>>();
    p0_kernel<<<5, 256>>>(Wq, bq, Wk, bk);
    p1_kernel<<<dim3(BT, 3), 256, S1_TOT>>>(x);
    attn_kernel<<<dim3(BT, 5), 256, SM_TOT>>>(mask, out);
}

// round 16
// speedup vs baseline: 1.0739x; 1.0739x over previous
#include <cuda_runtime.h>
#include <cuda_bf16.h>
#include <cstdint>

#define Nn 307
#define Cc 64
#define Tt 12
#define BT 96
#define NPAD 320
#define TN (Tt * Nn)

// ---------------- scratch ----------------
__device__ __nv_bfloat16 g_Aspl[64 * 128];  // row e: [At_hi(c) | At_lo(c)]
__device__ float g_u[64], g_v[64], g_cconst[1];
__device__ float g_xu[BT * NPAD];
__device__ float g_xv[BT * NPAD];
// PRE-SWIZZLED split buffers, 128B rows (8 chunks XOR row&7), hi/lo separate
__device__ __nv_bfloat16 g_Y[(size_t)BT * NPAD * 128];   // Y stays interleaved 256B rows
__device__ __nv_bfloat16 g_Xhi[(size_t)BT * NPAD * 64];
__device__ __nv_bfloat16 g_Xlo[(size_t)BT * NPAD * 64];

__device__ __forceinline__ uint32_t smem_u32(const void* p) {
    uint32_t a;
    asm("{ .reg .u64 t; cvta.to.shared.u64 t, %1; cvt.u32.u64 %0, t; }" : "=r"(a) : "l"(p));
    return a;
}
#define CPASYNC16(dst, src) \
    asm volatile("cp.async.cg.shared.global [%0], [%1], 16;" :: "r"(dst), "l"(src))
#define CPASYNC_COMMIT() asm volatile("cp.async.commit_group;" ::: "memory")
#define CPASYNC_WAIT_GROUP(n) asm volatile("cp.async.wait_group %0;" :: "n"(n) : "memory")

#define LDSM4(r0_, r1_, r2_, r3_, addr) \
    asm volatile("ldmatrix.sync.aligned.m8n8.x4.shared.b16 {%0,%1,%2,%3}, [%4];" \
        : "=r"(r0_), "=r"(r1_), "=r"(r2_), "=r"(r3_) : "r"(addr))

#define MMA16816(d, a, b0_, b1_) \
    asm volatile("mma.sync.aligned.m16n8k16.row.col.f32.bf16.bf16.f32 " \
        "{%0,%1,%2,%3}, {%4,%5,%6,%7}, {%8,%9}, {%0,%1,%2,%3};" \
        : "+f"((d)[0]), "+f"((d)[1]), "+f"((d)[2]), "+f"((d)[3]) \
        : "r"((a)[0]), "r"((a)[1]), "r"((a)[2]), "r"((a)[3]), "r"(b0_), "r"(b1_))

// ---------------- P0: (R12 measured version) ----------------
__global__ void __launch_bounds__(256)
p0_kernel(const float* __restrict__ Wq, const float* __restrict__ bq,
          const float* __restrict__ Wk, const float* __restrict__ bk)
{
    int blk = blockIdx.x, tid = threadIdx.x;
    const float s = 0.35355339059327373f;   // 1/sqrt(8)
    if (blk < 16) {
        int gid = blk * 256 + tid;
        int c = gid >> 6, e = gid & 63;
        float a = 0.f;
        #pragma unroll
        for (int k = 0; k < 64; k++)
            a += __ldg(&Wq[k * 64 + c]) * __ldg(&Wk[k * 64 + e]);
        a *= s;
        __nv_bfloat16 h = __float2bfloat16(a);
        __nv_bfloat16 l = __float2bfloat16(a - __bfloat162float(h));
        g_Aspl[e * 128 + c]      = h;
        g_Aspl[e * 128 + 64 + c] = l;
    } else {
        if (tid < 64) {
            float ua = 0.f;
            #pragma unroll
            for (int k = 0; k < 64; k++) ua += __ldg(&Wq[k * 64 + tid]) * __ldg(&bk[k]);
            g_u[tid] = ua * s;
        } else if (tid < 128) {
            int d = tid - 64;
            float va = 0.f;
            #pragma unroll
            for (int k = 0; k < 64; k++) va += __ldg(&Wk[k * 64 + d]) * __ldg(&bq[k]);
            g_v[d] = va * s;
        } else if (tid == 128) {
            float ca = 0.f;
            #pragma unroll
            for (int k = 0; k < 64; k++) ca += __ldg(&bq[k]) * __ldg(&bk[k]);
            g_cconst[0] = ca * s;
        }
    }
}

// ---------------- P1: convert x, Y via MMA (3-pass), xu/xv ----------------
// smem: xs fp32 32768 | XhiS 16384 | XloS 16384 | Aspl 16384 | uv 516; stage overlays xs
#define S1_XS   0
#define S1_XHI  32768
#define S1_XLO  49152
#define S1_A    65536
#define S1_UV   81920
#define S1_TOT  82560

__global__ void __launch_bounds__(256, 2)
p1_kernel(const float* __restrict__ x)
{
    extern __shared__ char smc[];
    float* xs = (float*)(smc + S1_XS);          // [c][n] stride 128
    float* uvs = (float*)(smc + S1_UV);
    int bt = blockIdx.x, rt = blockIdx.y;
    int b = bt / Tt, t = bt % Tt;
    int n0 = rt * 128;
    int tid = threadIdx.x, wid = tid >> 5, lane = tid & 31;
    int nrows = NPAD - n0; if (nrows > 128) nrows = 128;

    const float* xb = x + ((size_t)(b * Cc) * Tt + t) * Nn;
    for (int i = tid; i < 64 * 128; i += 256) {
        int c = i >> 7, n = i & 127;
        int ng = n0 + n;
        xs[i] = (ng < Nn) ? xb[(size_t)c * TN + ng] : 0.f;
    }
    {
        const uint4* asrc = (const uint4*)g_Aspl;
        uint4* adst = (uint4*)(smc + S1_A);
        for (int i = tid; i < 1024; i += 256) {
            int row = i >> 4, ci = i & 15;
            adst[(row << 4) + (ci ^ (row & 7))] = asrc[i];
        }
    }
    if (tid < 64) uvs[tid] = g_u[tid];
    else if (tid < 128) uvs[tid] = g_v[tid - 64];
    else if (tid == 128) uvs[128] = g_cconst[0];
    __syncthreads();

    // convert xs -> XhiS/XloS (128B rows, swizzled)
    for (int i = tid; i < 4096; i += 256) {
        int n = i & 127, cp = i >> 7;          // cp = col pair 0..31
        int c = cp * 2;
        float v0 = xs[c * 128 + n];
        float v1 = xs[(c + 1) * 128 + n];
        __nv_bfloat162 hh = __floats2bfloat162_rn(v0, v1);
        float l0 = v0 - __bfloat162float(hh.x);
        float l1 = v1 - __bfloat162float(hh.y);
        __nv_bfloat162 ll = __floats2bfloat162_rn(l0, l1);
        uint32_t a = (n << 7) + ((((cp >> 2)) ^ (n & 7)) << 4) + ((cp & 3) << 2);
        *(uint32_t*)(smc + S1_XHI + a) = *(uint32_t*)&hh;
        *(uint32_t*)(smc + S1_XLO + a) = *(uint32_t*)&ll;
    }
    __syncthreads();

    // xu / xv + copy Xhi/Xlo out (raw, pre-swizzled)
    {
        int r = tid & 127;
        int ng = n0 + r;
        if (ng < NPAD) {
            float a = 0.f;
            int woff = (tid < 128) ? 0 : 64;
            #pragma unroll 16
            for (int c = 0; c < 64; c++) a += xs[c * 128 + r] * uvs[woff + c];
            if (tid < 128) g_xu[bt * NPAD + ng] = a;
            else           g_xv[bt * NPAD + ng] = a + uvs[128];
        }
    }
    {
        uint4* gh = (uint4*)(g_Xhi + ((size_t)bt * NPAD + n0) * 64);
        uint4* gl = (uint4*)(g_Xlo + ((size_t)bt * NPAD + n0) * 64);
        const uint4* sh = (const uint4*)(smc + S1_XHI);
        const uint4* sl = (const uint4*)(smc + S1_XLO);
        int cnt = nrows * 8;
        for (int i = tid; i < cnt; i += 256) { gh[i] = sh[i]; gl[i] = sl[i]; }
    }

    // Y = X·Aᵀ, 3-pass: (Xhi,Ahi),(Xhi,Alo),(Xlo,Ahi). Warps 4x2: M=32, N=32
    uint32_t smbXhi = smem_u32(smc + S1_XHI);
    uint32_t smbXlo = smem_u32(smc + S1_XLO);
    uint32_t smbA = smem_u32(smc + S1_A);
    int wr = wid >> 1, wc = wid & 1;
    int aRow[2], bRow[2];
    #pragma unroll
    for (int mi = 0; mi < 2; mi++)
        aRow[mi] = wr * 32 + mi * 16 + ((lane >> 3) & 1) * 8 + (lane & 7);
    #pragma unroll
    for (int ni = 0; ni < 2; ni++)
        bRow[ni] = wc * 32 + ni * 16 + (lane >> 4) * 8 + (lane & 7);
    int aChf = lane >> 4, bChf = (lane >> 3) & 1;

    float accY[2][4][4];
    #pragma unroll
    for (int mi = 0; mi < 2; mi++)
        #pragma unroll
        for (int nq = 0; nq < 4; nq++)
            #pragma unroll
            for (int q = 0; q < 4; q++) accY[mi][nq][q] = 0.f;

    #pragma unroll
    for (int kk = 0; kk < 12; kk++) {
        int p = kk >> 2, q = kk & 3;
        uint32_t xbase = (p == 2) ? smbXlo : smbXhi;   // X lo on pass 2
        int bBase = (p == 1 ? 8 : 0) + q * 2;          // A lo on pass 1
        uint32_t a[2][4], bb[2][4];
        #pragma unroll
        for (int mi = 0; mi < 2; mi++) {
            int r = aRow[mi];
            uint32_t ad = xbase + (r << 7) + (((q * 2 + aChf) ^ (r & 7)) << 4);
            LDSM4(a[mi][0], a[mi][1], a[mi][2], a[mi][3], ad);
        }
        #pragma unroll
        for (int ni = 0; ni < 2; ni++) {
            int r = bRow[ni];
            uint32_t bd = smbA + (r << 8) + (((bBase + bChf) ^ (r & 7)) << 4);
            LDSM4(bb[ni][0], bb[ni][1], bb[ni][2], bb[ni][3], bd);
        }
        #pragma unroll
        for (int mi = 0; mi < 2; mi++)
            #pragma unroll
            for (int ni = 0; ni < 2; ni++) {
                MMA16816(accY[mi][ni * 2],     a[mi], bb[ni][0], bb[ni][1]);
                MMA16816(accY[mi][ni * 2 + 1], a[mi], bb[ni][2], bb[ni][3]);
            }
    }
    __syncthreads();   // xs readers done -> stage overlay safe

    // split accY -> stage (256B-row interleaved swizzle for Y), copy out
    {
        char* stg = smc + S1_XS;
        #pragma unroll
        for (int mi = 0; mi < 2; mi++) {
            #pragma unroll
            for (int nq = 0; nq < 4; nq++) {
                int col = wc * 32 + nq * 8 + (lane & 3) * 2;
                #pragma unroll
                for (int h = 0; h < 2; h++) {
                    int rl = wr * 32 + mi * 16 + (lane >> 2) + h * 8;
                    float a0 = accY[mi][nq][h * 2], a1 = accY[mi][nq][h * 2 + 1];
                    __nv_bfloat162 hh = __floats2bfloat162_rn(a0, a1);
                    float l0 = a0 - __bfloat162float(hh.x);
                    float l1 = a1 - __bfloat162float(hh.y);
                    __nv_bfloat162 ll = __floats2bfloat162_rn(l0, l1);
                    uint32_t off = (col & 7) << 1;
                    *(uint32_t*)(stg + (rl << 8) + ((((col >> 3))     ^ (rl & 7)) << 4) + off) = *(uint32_t*)&hh;
                    *(uint32_t*)(stg + (rl << 8) + (((8 + (col >> 3)) ^ (rl & 7)) << 4) + off) = *(uint32_t*)&ll;
                }
            }
        }
    }
    __syncthreads();
    {
        uint4* gy = (uint4*)(g_Y + ((size_t)bt * NPAD + n0) * 128);
        const uint4* s4 = (const uint4*)(smc + S1_XS);
        for (int i = tid; i < nrows * 16; i += 256) gy[i] = s4[i];
    }
}

// ---------------- attn: pipelined cp.async, 3-pass MMA, spill, softmax ----------------
#define SM_XHI 0              // 40960
#define SM_XLO 40960          // 40960
#define SM_Y   81920          // 16384
#define SM_TOT 98304
#define SROW 328

__global__ void __launch_bounds__(256, 2)
attn_kernel(const int* __restrict__ mask, float* __restrict__ out)
{
    extern __shared__ char smc[];
    int tid = threadIdx.x, wid = tid >> 5, lane = tid & 31;
    int bt = blockIdx.x, mt = blockIdx.y;
    int b = bt / Tt;
    int r0 = mt * 64;

    // ---- group 0: Y + Xhi ; group 1: Xlo ----
    {
        uint32_t yd = smem_u32(smc + SM_Y);
        const uint4* ysrc = (const uint4*)(g_Y + ((size_t)bt * NPAD + r0) * 128);
        for (int i = tid; i < 1024; i += 256)
            CPASYNC16(yd + i * 16, ysrc + i);
        uint32_t hd = smem_u32(smc + SM_XHI);
        const uint4* hsrc = (const uint4*)(g_Xhi + (size_t)bt * NPAD * 64);
        for (int i = tid; i < 2560; i += 256)
            CPASYNC16(hd + i * 16, hsrc + i);
        CPASYNC_COMMIT();
        uint32_t ld = smem_u32(smc + SM_XLO);
        const uint4* lsrc = (const uint4*)(g_Xlo + (size_t)bt * NPAD * 64);
        for (int i = tid; i < 2560; i += 256)
            CPASYNC16(ld + i * 16, lsrc + i);
        CPASYNC_COMMIT();
        CPASYNC_WAIT_GROUP(1);    // Y + Xhi landed
    }
    __syncthreads();

    int wr = wid >> 2, wc = wid & 3;
    int m0w = wr * 32, n0w = wc * 80;
    uint32_t smbY = smem_u32(smc + SM_Y);
    uint32_t smbXhi = smem_u32(smc + SM_XHI);
    uint32_t smbXlo = smem_u32(smc + SM_XLO);

    int aRowL[2], bRow[5];
    #pragma unroll
    for (int mi = 0; mi < 2; mi++)
        aRowL[mi] = m0w + mi * 16 + ((lane >> 3) & 1) * 8 + (lane & 7);
    #pragma unroll
    for (int pi = 0; pi < 5; pi++)
        bRow[pi] = n0w + pi * 16 + (lane >> 4) * 8 + (lane & 7);
    int aChf = lane >> 4;
    int bChf = (lane >> 3) & 1;

    float acc[2][10][4];
    #pragma unroll
    for (int mi = 0; mi < 2; mi++)
        #pragma unroll
        for (int ni = 0; ni < 10; ni++)
            #pragma unroll
            for (int q = 0; q < 4; q++) acc[mi][ni][q] = 0.f;

    // pass order: 0 (Yhi·Xhi), 2 (Ylo·Xhi), then 1 (Yhi·Xlo) after group-1 wait
    #pragma unroll
    for (int pp = 0; pp < 3; pp++) {
        int p = (pp == 0) ? 0 : (pp == 1) ? 2 : 1;
        if (pp == 2) {
            CPASYNC_WAIT_GROUP(0);
            __syncthreads();
        }
        uint32_t xbase = (p == 1) ? smbXlo : smbXhi;
        int aBase = (p == 2 ? 8 : 0);
        #pragma unroll
        for (int q = 0; q < 4; q++) {
            uint32_t a[2][4], bf[5][4];
            #pragma unroll
            for (int mi = 0; mi < 2; mi++) {
                int r = aRowL[mi];
                uint32_t ad = smbY + (r << 8) + (((aBase + q * 2 + aChf) ^ (r & 7)) << 4);
                LDSM4(a[mi][0], a[mi][1], a[mi][2], a[mi][3], ad);
            }
            #pragma unroll
            for (int pi = 0; pi < 5; pi++) {
                int r = bRow[pi];
                uint32_t bd = xbase + (r << 7) + (((q * 2 + bChf) ^ (r & 7)) << 4);
                LDSM4(bf[pi][0], bf[pi][1], bf[pi][2], bf[pi][3], bd);
            }
            #pragma unroll
            for (int mi = 0; mi < 2; mi++)
                #pragma unroll
                for (int pi = 0; pi < 5; pi++) {
                    MMA16816(acc[mi][2 * pi],     a[mi], bf[pi][0], bf[pi][1]);
                    MMA16816(acc[mi][2 * pi + 1], a[mi], bf[pi][2], bf[pi][3]);
                }
        }
    }
    __syncthreads();

    // ---- spill scores (overlay X regions) ----
    float* S = (float*)smc;
    {
        int rbase = m0w + (lane >> 2);
        int cbase = n0w + (lane & 3) * 2;
        #pragma unroll
        for (int mi = 0; mi < 2; mi++) {
            #pragma unroll
            for (int ni = 0; ni < 10; ni++) {
                int c = cbase + ni * 8;
                *(float2*)&S[(rbase + mi * 16) * SROW + c]     = make_float2(acc[mi][ni][0], acc[mi][ni][1]);
                *(float2*)&S[(rbase + mi * 16 + 8) * SROW + c] = make_float2(acc[mi][ni][2], acc[mi][ni][3]);
            }
        }
    }
    __syncthreads();

    // ---- softmax (warp per row, 2 rows in flight) ----
    float xv10[10];
    #pragma unroll
    for (int it = 0; it < 10; it++)
        xv10[it] = g_xv[bt * NPAD + lane + it * 32];

    #pragma unroll 2
    for (int r = wid; r < 64; r += 8) {
        int n = r0 + r;
        if (n >= Nn) continue;
        float xun = g_xu[bt * NPAD + n];
        const int* mrow = mask + ((size_t)b * Nn + n) * Nn;
        float v[10];
        float mx = -3.4e38f;
        #pragma unroll
        for (int it = 0; it < 10; it++) {
            int m = lane + it * 32;
            float s = -3.4e38f;
            if (m < Nn) s = mrow[m] ? (S[r * SROW + m] + xun + xv10[it]) : -1e9f;
            v[it] = s;
            mx = fmaxf(mx, s);
        }
        #pragma unroll
        for (int o = 16; o; o >>= 1)
            mx = fmaxf(mx, __shfl_xor_sync(0xffffffffu, mx, o));
        float ssum = 0.f;
        #pragma unroll
        for (int it = 0; it < 10; it++) {
            float e = __expf(v[it] - mx);
            v[it] = e;
            ssum += e;
        }
        #pragma unroll
        for (int o = 16; o; o >>= 1)
            ssum += __shfl_xor_sync(0xffffffffu, ssum, o);
        float inv = 1.0f / ssum;
        float* orow = out + ((size_t)bt * Nn + n) * Nn;
        #pragma unroll
        for (int it = 0; it < 10; it++) {
            int m = lane + it * 32;
            if (m < Nn) orow[m] = v[it] * inv;
        }
    }
}

extern "C" void kernel_launch(void* const* d_in, const int* in_sizes, int n_in,
                              void* d_out, int out_size)
{
    const float* x    = (const float*)d_in[0];
    const int*   mask = (const int*)  d_in[1];
    const float* Wq   = (const float*)d_in[2];
    const float* bq   = (const float*)d_in[3];
    const float* Wk   = (const float*)d_in[4];
    const float* bk   = (const float*)d_in[5];
    float* out = (float*)d_out;

    cudaFuncSetAttribute(p1_kernel, cudaFuncAttributeMaxDynamicSharedMemorySize, S1_TOT);
    cudaFuncSetAttribute(attn_kernel, cudaFuncAttributeMaxDynamicSharedMemorySize, SM_TOT);

    p0_kernel<<<17, 256>>>(Wq, bq, Wk, bk);
    p1_kernel<<<dim3(BT, 3), 256, S1_TOT>>>(x);
    attn_kernel<<<dim3(BT, 5), 256, SM_TOT>>>(mask, out);
}